// round 14
// baseline (speedup 1.0000x reference)
#include <cuda_runtime.h>
#include <cuda_bf16.h>
#include <math.h>
#include <float.h>
#include <stdint.h>

// ============================================================================
// VectorQuantizer: bf16 mma.sync ranking + exact fp32 candidate rescore.
// R14: barrier-free main loop. Each warp owns a 128-code range and loads its
// B fragments DIRECTLY from gmem into registers (double-buffered one slice
// ahead). No cp.async, no B smem, no __syncthreads in the main loop -> warps
// free-run and cover each other's latency (the lockstep fill loop was the
// config-invariant ~230us wall in R5-R13).
// BM=64 rows/CTA, 256 threads (8 warps); warp tile 64 rows x 16 codes.
// dist(n,k) = |x|^2 - 2 x.c + |c|^2 ; argmin over (cnorm[k] - 2*dot).
// Lanes track top-2 packed keys per (row-slot); 64 candidates/row; rows with
// >1 candidate within EPS=0.1 re-decided by exact fp32 dots.
// out = [ste, perplexity, codebook_loss, commitment_loss]
// ============================================================================

#define D_DIM   256
#define K_CODES 1024
#define BM      64
#define THREADS 256
#define NSLICES 32              // per warp: 8 sub-chunks of 16 codes x 4 d-slices
#define EPS_MARGIN 0.1f

#define AST 264                 // A smem row stride (bf16 elems)

#define OFS_AH    0
#define ABYTES    (BM * AST * 2)                     // 33792
#define OFS_CN    (OFS_AH + ABYTES)                  // cnorm: 4KB
#define OFS_CAND  (OFS_CN + K_CODES * 4)             // 37888
#define CAND_PER_ROW 64
#define OFS_BK    (OFS_CAND + BM * CAND_PER_ROW * 4) // 54272
#define SMEM_MAIN (OFS_BK + BM * 4)                  // 54528

__device__ float          g_cT[K_CODES * D_DIM];
__device__ __nv_bfloat16  g_cbh[K_CODES * D_DIM];
__device__ float          g_cnorm[K_CODES];
__device__ int            g_counts[K_CODES];
__device__ float          g_sumsq;

// ---------------------------------------------------------------------------
__device__ __forceinline__ uint32_t smem_u32(const void* p) {
    uint32_t a;
    asm("{ .reg .u64 t; cvta.to.shared.u64 t, %1; cvt.u32.u64 %0, t; }"
        : "=r"(a) : "l"(p));
    return a;
}

__device__ __forceinline__ void ldmx4(uint32_t& r0, uint32_t& r1,
                                      uint32_t& r2, uint32_t& r3, uint32_t a) {
    asm volatile("ldmatrix.sync.aligned.m8n8.x4.shared.b16 {%0,%1,%2,%3}, [%4];"
                 : "=r"(r0), "=r"(r1), "=r"(r2), "=r"(r3) : "r"(a));
}

#define MMA_BF16(c, a, b)                                                     \
    asm volatile("mma.sync.aligned.m16n8k16.row.col.f32.bf16.bf16.f32 "       \
                 "{%0,%1,%2,%3}, {%4,%5,%6,%7}, {%8,%9}, {%0,%1,%2,%3};"      \
                 : "+f"((c)[0]), "+f"((c)[1]), "+f"((c)[2]), "+f"((c)[3])     \
                 : "r"((a)[0]), "r"((a)[1]), "r"((a)[2]), "r"((a)[3]),        \
                   "r"((b)[0]), "r"((b)[1]))

// monotone float->uint encode (order-preserving) and its inverse
__device__ __forceinline__ uint32_t fenc(uint32_t u) {
    uint32_t m = (uint32_t)((int32_t)u >> 31);
    return u ^ (m | 0x80000000u);
}
__device__ __forceinline__ uint32_t fdec(uint32_t e) {
    return (e & 0x80000000u) ? (e ^ 0x80000000u) : ~e;
}

// ============================================================================
__global__ void k_init() {
    int t = threadIdx.x;
    if (t < K_CODES) g_counts[t] = 0;
    if (t == 0) g_sumsq = 0.0f;
}

__global__ void k_cnorm(const float* __restrict__ cb) {
    int k = blockIdx.x * blockDim.x + threadIdx.x;
    float s = 0.0f;
    #pragma unroll 8
    for (int d = 0; d < D_DIM; d++) {
        float v = cb[d * K_CODES + k];
        s += v * v;
    }
    g_cnorm[k] = s;
}

__global__ void k_prep(const float* __restrict__ cb) {
    __shared__ float t[32][33];
    int k = blockIdx.x * 32 + threadIdx.x;
    int d = blockIdx.y * 32 + threadIdx.y;
    t[threadIdx.y][threadIdx.x] = cb[d * K_CODES + k];
    __syncthreads();
    int ko = blockIdx.x * 32 + threadIdx.y;
    int dd = blockIdx.y * 32 + threadIdx.x;
    float v = t[threadIdx.x][threadIdx.y];
    size_t o = (size_t)ko * D_DIM + dd;
    g_cT[o] = v;
    g_cbh[o] = __float2bfloat16(v);
}

// ============================================================================
__global__ __launch_bounds__(THREADS, 2)
void k_main(const float* __restrict__ inputs, float* __restrict__ out) {
    extern __shared__ char smem[];
    const uint32_t sb = smem_u32(smem);
    const int tid    = threadIdx.x;
    const int wid    = tid >> 5;          // warp w owns codes [w*128, w*128+128)
    const int lane   = tid & 31;
    const int g      = lane >> 2;
    const int t2     = lane & 3;
    const int rowBase = blockIdx.x * BM;

    float*    s_cnorm = (float*)(smem + OFS_CN);
    uint32_t* s_cand  = (uint32_t*)(smem + OFS_CAND);
    int*      s_bk    = (int*)(smem + OFS_BK);

    // ---- A conversion: 64x256 fp32 -> bf16 in smem; cnorm -> smem ----
    {
        const float4* in4 = (const float4*)(inputs + (size_t)rowBase * D_DIM);
        #pragma unroll
        for (int i = 0; i < 16; i++) {
            int idx = tid + i * THREADS;
            int r = idx >> 6;
            int d = (idx & 63) << 2;
            float4 v = in4[idx];
            __nv_bfloat16 h0 = __float2bfloat16(v.x);
            __nv_bfloat16 h1 = __float2bfloat16(v.y);
            __nv_bfloat16 h2 = __float2bfloat16(v.z);
            __nv_bfloat16 h3 = __float2bfloat16(v.w);
            uint64_t ph = (uint64_t)__bfloat16_as_ushort(h0)
                        | ((uint64_t)__bfloat16_as_ushort(h1) << 16)
                        | ((uint64_t)__bfloat16_as_ushort(h2) << 32)
                        | ((uint64_t)__bfloat16_as_ushort(h3) << 48);
            *(uint64_t*)(smem + OFS_AH + (uint32_t)(r * AST + d) * 2) = ph;
        }
        #pragma unroll
        for (int i = 0; i < K_CODES / THREADS; i++)
            s_cnorm[tid + i * THREADS] = g_cnorm[tid + i * THREADS];
    }
    __syncthreads();   // the ONLY barrier before the reductions

    // ---- per-warp B base pointer (bytes) ----
    // lane reads code (cbase + nt*8 + g) at d offsets (dbase + 2*t2) and (+8)
    const char* bbase = (const char*)g_cbh
                      + ((size_t)(wid * 128 + g) * D_DIM + 2 * t2) * 2;

    const int laneRowA = (lane & 7) + ((lane >> 3) & 1) * 8;
    const int laneColA = ((lane >> 4) & 1) * 8;

    // B register ring: [buf][kstep][nt][2]
    uint32_t breg[2][4][2][2];

    // acc[mt][nt][4]: rows mt*16 + g + 8*(e>>1), codes nt*8 + t2*2 + (e&1)
    float acc[4][2][4];
    #pragma unroll
    for (int mt = 0; mt < 4; mt++)
        #pragma unroll
        for (int nt = 0; nt < 2; nt++)
            #pragma unroll
            for (int e = 0; e < 4; e++) acc[mt][nt][e] = 0.0f;

    // top-2 packed keys per row-slot (8 slots: mt*2 + e_hi)
    uint32_t K1[8], K2[8];
    #pragma unroll
    for (int b = 0; b < 8; b++) { K1[b] = 0xFFFFFFFFu; K2[b] = 0xFFFFFFFFu; }

    // slice s: sc = s>>2 (16-code sub-chunk), ds = s&3 (64-d slice)
    auto loadB = [&](int s, int buf) {
        const int sc = s >> 2, ds = s & 3;
        const char* p = bbase + (size_t)(sc * 16) * (D_DIM * 2) + (ds * 64) * 2;
        #pragma unroll
        for (int kstep = 0; kstep < 4; kstep++)
            #pragma unroll
            for (int nt = 0; nt < 2; nt++) {
                const char* q = p + (size_t)(nt * 8) * (D_DIM * 2) + (kstep * 16) * 2;
                breg[buf][kstep][nt][0] = __ldg((const uint32_t*)q);
                breg[buf][kstep][nt][1] = __ldg((const uint32_t*)(q + 16));
            }
    };

    loadB(0, 0);

    for (int s = 0; s < NSLICES; s++) {
        const int buf = s & 1;
        if (s + 1 < NSLICES) loadB(s + 1, buf ^ 1);

        const int ds = s & 3;
        #pragma unroll
        for (int kstep = 0; kstep < 4; kstep++) {
            const int ka = ds * 64 + kstep * 16;
            uint32_t ah[4][4];
            #pragma unroll
            for (int mt = 0; mt < 4; mt++) {
                uint32_t ro = (uint32_t)((mt * 16 + laneRowA) * AST + ka + laneColA) * 2;
                ldmx4(ah[mt][0], ah[mt][1], ah[mt][2], ah[mt][3], sb + OFS_AH + ro);
            }
            #pragma unroll
            for (int mt = 0; mt < 4; mt++)
                #pragma unroll
                for (int nt = 0; nt < 2; nt++)
                    MMA_BF16(acc[mt][nt], ah[mt], breg[buf][kstep][nt]);
        }

        if ((s & 3) == 3) {   // sub-chunk complete: fold 16 codes
            const int sc = s >> 2;
            #pragma unroll
            for (int mt = 0; mt < 4; mt++)
                #pragma unroll
                for (int nt = 0; nt < 2; nt++)
                    #pragma unroll
                    for (int e = 0; e < 4; e++) {
                        int k = wid * 128 + sc * 16 + nt * 8 + t2 * 2 + (e & 1);
                        float dist = fmaf(-2.0f, acc[mt][nt][e], s_cnorm[k]);
                        uint32_t key = (fenc(__float_as_uint(dist)) & 0xFFFFFC00u)
                                     | (uint32_t)k;
                        int b = mt * 2 + (e >> 1);
                        if (key < K1[b])      { K2[b] = K1[b]; K1[b] = key; }
                        else if (key < K2[b]) { K2[b] = key; }
                        acc[mt][nt][e] = 0.0f;
                    }
        }
    }

    // ---- dump per-lane top-2 per row-slot: 8 warps x 4 t2 x 2 = 64 / row ----
    #pragma unroll
    for (int b = 0; b < 8; b++) {
        int mt = b >> 1, hi = b & 1;
        int row = mt * 16 + g + hi * 8;
        int col = wid * 8 + t2 * 2;
        s_cand[row * CAND_PER_ROW + col + 0] = K1[b];
        s_cand[row * CAND_PER_ROW + col + 1] = K2[b];
    }
    __syncthreads();

    // ---- per-row: candidate window + exact fp32 rescore ----
    if (tid < BM) {
        const uint32_t* ck = s_cand + tid * CAND_PER_ROW;
        uint32_t kmin = 0xFFFFFFFFu;
        #pragma unroll 8
        for (int j = 0; j < CAND_PER_ROW; j++) {
            uint32_t v = ck[j];
            if (v < kmin) kmin = v;
        }
        float vmin = __uint_as_float(fdec(kmin & 0xFFFFFC00u));
        float thr  = vmin + EPS_MARGIN;
        uint32_t thrkey = fenc(__float_as_uint(thr)) | 0x3FFu;
        int ncand = 0;
        #pragma unroll 8
        for (int j = 0; j < CAND_PER_ROW; j++)
            ncand += (ck[j] <= thrkey);
        int bk = (int)(kmin & 0x3FFu);
        if (ncand > 1) {
            const float* xr = inputs + (size_t)(rowBase + tid) * D_DIM;
            float beste = FLT_MAX;
            int   bestk = 0x7FFFFFFF;
            for (int j = 0; j < CAND_PER_ROW; j++) {
                if (ck[j] > thrkey) continue;
                int k = (int)(ck[j] & 0x3FFu);
                if (k == bestk) continue;
                const float* cr = g_cT + (size_t)k * D_DIM;
                float dot = 0.0f;
                #pragma unroll 8
                for (int d = 0; d < D_DIM; d++)
                    dot = fmaf(__ldg(xr + d), __ldg(cr + d), dot);
                float e = fmaf(-2.0f, dot, s_cnorm[k]);
                if (e < beste || (e == beste && k < bestk)) { beste = e; bestk = k; }
            }
            bk = bestk;
        }
        s_bk[tid] = bk;
        atomicAdd(&g_counts[bk], 1);
    }
    __syncthreads();

    // ---- epilogue: ste + sum (q-x)^2, exact fp32 x from gmem ----
    {
        float ss = 0.0f;
        #pragma unroll
        for (int rr = 0; rr < 8; rr++) {
            const int r = wid * 8 + rr;
            const int bk = s_bk[r];
            const float4* x4 = (const float4*)(inputs + (size_t)(rowBase + r) * D_DIM);
            const float4* q4 = (const float4*)(g_cT + (size_t)bk * D_DIM);
            float4* o4 = (float4*)(out + (size_t)(rowBase + r) * D_DIM);
            #pragma unroll
            for (int h = 0; h < 2; h++) {
                int d4 = lane + h * 32;
                float4 x = x4[d4];
                float4 q = q4[d4];
                float d0 = q.x - x.x, d1 = q.y - x.y, d2 = q.z - x.z, d3 = q.w - x.w;
                float4 o;
                o.x = x.x + d0; o.y = x.y + d1; o.z = x.z + d2; o.w = x.w + d3;
                o4[d4] = o;
                ss = fmaf(d0, d0, ss); ss = fmaf(d1, d1, ss);
                ss = fmaf(d2, d2, ss); ss = fmaf(d3, d3, ss);
            }
        }
        #pragma unroll
        for (int o = 16; o; o >>= 1)
            ss += __shfl_xor_sync(0xFFFFFFFFu, ss, o);
        if (lane == 0) atomicAdd(&g_sumsq, ss);
    }
}

// ============================================================================
__global__ void k_final(float* __restrict__ out, int rows) {
    __shared__ float red[32];
    int tid = threadIdx.x;
    float p = (float)g_counts[tid] / (float)rows;
    float term = -p * logf(p + 1e-10f);
    #pragma unroll
    for (int o = 16; o; o >>= 1)
        term += __shfl_xor_sync(0xFFFFFFFFu, term, o);
    if ((tid & 31) == 0) red[tid >> 5] = term;
    __syncthreads();
    if (tid < 32) {
        float v = red[tid];
        #pragma unroll
        for (int o = 16; o; o >>= 1)
            v += __shfl_xor_sync(0xFFFFFFFFu, v, o);
        if (tid == 0) {
            float mean = g_sumsq / ((float)rows * (float)D_DIM);
            size_t base = (size_t)rows * D_DIM;
            out[base + 0] = expf(v);
            out[base + 1] = mean;
            out[base + 2] = 0.25f * mean;
        }
    }
}

// ============================================================================
extern "C" void kernel_launch(void* const* d_in, const int* in_sizes, int n_in,
                              void* d_out, int out_size) {
    const float* inputs   = (const float*)d_in[0];
    const float* codebook = (const float*)d_in[1];
    float* out = (float*)d_out;
    int rows = in_sizes[0] / D_DIM;

    cudaFuncSetAttribute(k_main, cudaFuncAttributeMaxDynamicSharedMemorySize, SMEM_MAIN);

    k_init<<<1, 1024>>>();
    k_cnorm<<<K_CODES / 256, 256>>>(codebook);
    k_prep<<<dim3(K_CODES / 32, D_DIM / 32), dim3(32, 32)>>>(codebook);
    k_main<<<rows / BM, THREADS, SMEM_MAIN>>>(inputs, out);
    k_final<<<1, 1024>>>(out, rows);
}

// round 16
// speedup vs baseline: 1.6228x; 1.6228x over previous
#include <cuda_runtime.h>
#include <cuda_bf16.h>
#include <math.h>
#include <float.h>
#include <stdint.h>

// ============================================================================
// VectorQuantizer, split-K two-phase (re-run of R15; infra failure last round).
// Phase A (k_rank): 2048 CTAs = 512 row-tiles x 4 code-groups. Each CTA ranks
//   64 rows against 256 codes via bf16 mma.sync (R13 inner loop, NSLICES=8,
//   4-deep cp.async ring), folds per-lane top-3 keys, writes per-row top-4
//   candidates for its group to gmem (16 candidates/row globally).
// Phase B (k_tail): 512 CTAs. Per row: merge 16 keys, EPS=0.1 window, exact
//   fp32 rescore when >1 candidate in window; then ste + losses epilogue.
// dist(n,k) = |x|^2 - 2 x.c + |c|^2 ; argmin over (cnorm[k] - 2*dot).
// out = [ste, perplexity, codebook_loss, commitment_loss]
// ============================================================================

#define D_DIM   256
#define K_CODES 1024
#define BM      64
#define THREADS 256
#define NGROUP  4
#define KG_CODES (K_CODES / NGROUP)       // 256 codes per group
#define NSLICES 8                         // 2 chunks x 4 d-slices
#define EPS_MARGIN 0.1f

#define AST 264                            // A smem row stride (bf16 elems)
#define NBUF 4

#define OFS_AH    0
#define ABYTES    (BM * AST * 2)                     // 33792
#define OFS_B     (OFS_AH + ABYTES)
#define BBYTES    (128 * 128)                        // 16384 per slice buffer
#define OFS_CAND  OFS_B                              // overlay (post-loop only)
#define CAND_PER_ROW 48
#define SMEM_MAIN (OFS_B + NBUF * BBYTES)            // 99328

__device__ float          g_cT[K_CODES * D_DIM];
__device__ __nv_bfloat16  g_cbh[K_CODES * D_DIM];
__device__ float          g_cnorm[K_CODES];
__device__ int            g_counts[K_CODES];
__device__ float          g_sumsq;
__device__ uint32_t       g_cand[32768 * 16];        // 16 candidate keys / row

// ---------------------------------------------------------------------------
__device__ __forceinline__ uint32_t smem_u32(const void* p) {
    uint32_t a;
    asm("{ .reg .u64 t; cvta.to.shared.u64 t, %1; cvt.u32.u64 %0, t; }"
        : "=r"(a) : "l"(p));
    return a;
}

#define CP16(sa, ga) \
    asm volatile("cp.async.cg.shared.global [%0], [%1], 16;" \
                 :: "r"(sa), "l"(ga) : "memory")
#define CP_COMMIT() asm volatile("cp.async.commit_group;" ::: "memory")
#define CP_WAIT2()  asm volatile("cp.async.wait_group 2;" ::: "memory")

__device__ __forceinline__ void ldmx4(uint32_t& r0, uint32_t& r1,
                                      uint32_t& r2, uint32_t& r3, uint32_t a) {
    asm volatile("ldmatrix.sync.aligned.m8n8.x4.shared.b16 {%0,%1,%2,%3}, [%4];"
                 : "=r"(r0), "=r"(r1), "=r"(r2), "=r"(r3) : "r"(a));
}

#define MMA_BF16(c, a, b)                                                     \
    asm volatile("mma.sync.aligned.m16n8k16.row.col.f32.bf16.bf16.f32 "       \
                 "{%0,%1,%2,%3}, {%4,%5,%6,%7}, {%8,%9}, {%0,%1,%2,%3};"      \
                 : "+f"((c)[0]), "+f"((c)[1]), "+f"((c)[2]), "+f"((c)[3])     \
                 : "r"((a)[0]), "r"((a)[1]), "r"((a)[2]), "r"((a)[3]),        \
                   "r"((b)[0]), "r"((b)[1]))

// monotone float->uint encode (order-preserving) and its inverse
__device__ __forceinline__ uint32_t fenc(uint32_t u) {
    uint32_t m = (uint32_t)((int32_t)u >> 31);
    return u ^ (m | 0x80000000u);
}
__device__ __forceinline__ uint32_t fdec(uint32_t e) {
    return (e & 0x80000000u) ? (e ^ 0x80000000u) : ~e;
}

// ============================================================================
__global__ void k_init() {
    int t = threadIdx.x;
    if (t < K_CODES) g_counts[t] = 0;
    if (t == 0) g_sumsq = 0.0f;
}

__global__ void k_cnorm(const float* __restrict__ cb) {
    int k = blockIdx.x * blockDim.x + threadIdx.x;
    float s = 0.0f;
    #pragma unroll 8
    for (int d = 0; d < D_DIM; d++) {
        float v = cb[d * K_CODES + k];
        s += v * v;
    }
    g_cnorm[k] = s;
}

__global__ void k_prep(const float* __restrict__ cb) {
    __shared__ float t[32][33];
    int k = blockIdx.x * 32 + threadIdx.x;
    int d = blockIdx.y * 32 + threadIdx.y;
    t[threadIdx.y][threadIdx.x] = cb[d * K_CODES + k];
    __syncthreads();
    int ko = blockIdx.x * 32 + threadIdx.y;
    int dd = blockIdx.y * 32 + threadIdx.x;
    float v = t[threadIdx.x][threadIdx.y];
    size_t o = (size_t)ko * D_DIM + dd;
    g_cT[o] = v;
    g_cbh[o] = __float2bfloat16(v);
}

// ============================================================================
// Phase A: rank 64 rows x 256 codes. grid = 512 row-tiles x 4 groups.
// ============================================================================
__global__ __launch_bounds__(THREADS, 2)
void k_rank(const float* __restrict__ inputs) {
    extern __shared__ char smem[];
    const uint32_t sb = smem_u32(smem);
    const int tid    = threadIdx.x;
    const int wid    = tid >> 5;
    const int lane   = tid & 31;
    const int warp_m = wid & 1;
    const int warp_n = wid >> 1;
    const int g      = lane >> 2;
    const int t2     = lane & 3;
    const int rowTile = blockIdx.x >> 2;
    const int kg      = blockIdx.x & 3;
    const int rowBase = rowTile * BM;
    const int kgbase  = kg * KG_CODES;

    uint32_t* s_cand = (uint32_t*)(smem + OFS_CAND);

    // ---- A conversion: 64x256 fp32 -> bf16 in smem ----
    {
        const float4* in4 = (const float4*)(inputs + (size_t)rowBase * D_DIM);
        #pragma unroll
        for (int i = 0; i < 16; i++) {
            int idx = tid + i * THREADS;
            int r = idx >> 6;
            int d = (idx & 63) << 2;
            float4 v = in4[idx];
            __nv_bfloat16 h0 = __float2bfloat16(v.x);
            __nv_bfloat16 h1 = __float2bfloat16(v.y);
            __nv_bfloat16 h2 = __float2bfloat16(v.z);
            __nv_bfloat16 h3 = __float2bfloat16(v.w);
            uint64_t ph = (uint64_t)__bfloat16_as_ushort(h0)
                        | ((uint64_t)__bfloat16_as_ushort(h1) << 16)
                        | ((uint64_t)__bfloat16_as_ushort(h2) << 32)
                        | ((uint64_t)__bfloat16_as_ushort(h3) << 48);
            *(uint64_t*)(smem + OFS_AH + (uint32_t)(r * AST + d) * 2) = ph;
        }
    }

    // slice s: chunk = s>>2 (128 codes), ds = s&3 (64 d); swizzled 128B rows
    auto fill = [&](int s, int buf) {
        int chunk = s >> 2, ds = s & 3;
        const char* src = (const char*)(g_cbh
                        + (size_t)(kgbase + chunk * 128) * D_DIM + ds * 64);
        uint32_t dst = sb + OFS_B + (uint32_t)buf * BBYTES;
        #pragma unroll
        for (int i = 0; i < 4; i++) {
            int t = tid + i * THREADS;        // 0..1023
            int code = t >> 3, seg = t & 7;
            uint32_t so = (uint32_t)(code * 128 + ((seg ^ (code & 7)) << 4));
            CP16(dst + so, src + (size_t)code * (D_DIM * 2) + seg * 16);
        }
    };
    fill(0, 0); CP_COMMIT();
    fill(1, 1); CP_COMMIT();
    fill(2, 2); CP_COMMIT();

    const int laneRowA = (lane & 7) + ((lane >> 3) & 1) * 8;
    const int laneColA = ((lane >> 4) & 1) * 8;
    const int laneRowB = (lane & 7) + ((lane >> 4) & 1) * 8;
    const int laneColByteB = ((lane >> 3) & 1) * 16;

    float acc[2][4][4];
    #pragma unroll
    for (int mt = 0; mt < 2; mt++)
        #pragma unroll
        for (int nt = 0; nt < 4; nt++)
            #pragma unroll
            for (int e = 0; e < 4; e++) acc[mt][nt][e] = 0.0f;

    // per-slot top-3 packed keys (4 slots: mt*2 + e_hi)
    uint32_t K1[4], K2[4], K3[4];
    #pragma unroll
    for (int b = 0; b < 4; b++) { K1[b] = 0xFFFFFFFFu; K2[b] = 0xFFFFFFFFu; K3[b] = 0xFFFFFFFFu; }

    for (int s = 0; s < NSLICES; s++) {
        CP_WAIT2();
        __syncthreads();
        if (s + 3 < NSLICES) fill(s + 3, (s + 3) & 3);
        CP_COMMIT();

        const uint32_t bB = sb + OFS_B + (uint32_t)(s & 3) * BBYTES;
        const int ds = s & 3;

        #pragma unroll
        for (int kstep = 0; kstep < 4; kstep++) {
            const int ka = ds * 64 + kstep * 16;
            const int cbyte = kstep * 32 + laneColByteB;

            uint32_t ah[2][4], bh[4][2];
            #pragma unroll
            for (int p = 0; p < 2; p++) {
                uint32_t row = (uint32_t)(warp_n * 32 + p * 16 + laneRowB);
                uint32_t addr = bB + row * 128 + (uint32_t)(cbyte ^ ((row & 7) << 4));
                ldmx4(bh[p*2][0], bh[p*2][1], bh[p*2+1][0], bh[p*2+1][1], addr);
            }
            #pragma unroll
            for (int mt = 0; mt < 2; mt++) {
                uint32_t ro = (uint32_t)((warp_m * 32 + mt * 16 + laneRowA) * AST
                                         + ka + laneColA) * 2;
                ldmx4(ah[mt][0], ah[mt][1], ah[mt][2], ah[mt][3], sb + OFS_AH + ro);
            }
            #pragma unroll
            for (int mt = 0; mt < 2; mt++)
                #pragma unroll
                for (int nt = 0; nt < 4; nt++)
                    MMA_BF16(acc[mt][nt], ah[mt], bh[nt]);
        }

        if ((s & 3) == 3) {
            const int chunk = s >> 2;
            #pragma unroll
            for (int mt = 0; mt < 2; mt++)
                #pragma unroll
                for (int nt = 0; nt < 4; nt++)
                    #pragma unroll
                    for (int e = 0; e < 4; e++) {
                        int k = kgbase + chunk * 128 + warp_n * 32 + nt * 8
                              + t2 * 2 + (e & 1);
                        float dist = fmaf(-2.0f, acc[mt][nt][e], __ldg(g_cnorm + k));
                        uint32_t key = (fenc(__float_as_uint(dist)) & 0xFFFFFC00u)
                                     | (uint32_t)k;
                        int b = mt * 2 + (e >> 1);
                        if (key < K1[b])      { K3[b] = K2[b]; K2[b] = K1[b]; K1[b] = key; }
                        else if (key < K2[b]) { K3[b] = K2[b]; K2[b] = key; }
                        else if (key < K3[b]) { K3[b] = key; }
                        acc[mt][nt][e] = 0.0f;
                    }
        }
    }
    __syncthreads();   // loop done; B ring dead -> reuse as candidate area

    // ---- dump per-lane top-3 (48 per row for this group) ----
    #pragma unroll
    for (int b = 0; b < 4; b++) {
        int mt = b >> 1, hi = b & 1;
        int row = warp_m * 32 + mt * 16 + g + hi * 8;
        int col = warp_n * 12 + t2 * 3;
        s_cand[row * CAND_PER_ROW + col + 0] = K1[b];
        s_cand[row * CAND_PER_ROW + col + 1] = K2[b];
        s_cand[row * CAND_PER_ROW + col + 2] = K3[b];
    }
    __syncthreads();

    // ---- per-row top-4 of 48 -> gmem candidates for this group ----
    if (tid < BM) {
        const uint32_t* ck = s_cand + tid * CAND_PER_ROW;
        uint32_t c0 = 0xFFFFFFFFu, c1 = 0xFFFFFFFFu,
                 c2 = 0xFFFFFFFFu, c3 = 0xFFFFFFFFu;
        #pragma unroll 8
        for (int j = 0; j < CAND_PER_ROW; j++) {
            uint32_t v = ck[j];
            if (v < c0)      { c3 = c2; c2 = c1; c1 = c0; c0 = v; }
            else if (v < c1) { c3 = c2; c2 = c1; c1 = v; }
            else if (v < c2) { c3 = c2; c2 = v; }
            else if (v < c3) { c3 = v; }
        }
        uint32_t* dst = g_cand + (size_t)(rowBase + tid) * 16 + kg * 4;
        dst[0] = c0; dst[1] = c1; dst[2] = c2; dst[3] = c3;
    }
}

// ============================================================================
// Phase B: merge candidates, rescore, epilogue. grid = 512.
// ============================================================================
__global__ __launch_bounds__(THREADS, 2)
void k_tail(const float* __restrict__ inputs, float* __restrict__ out) {
    __shared__ int s_bk[BM];
    const int tid  = threadIdx.x;
    const int wid  = tid >> 5;
    const int lane = tid & 31;
    const int rowBase = blockIdx.x * BM;

    if (tid < BM) {
        const uint32_t* ck = g_cand + (size_t)(rowBase + tid) * 16;
        uint32_t keys[16];
        #pragma unroll
        for (int j = 0; j < 16; j++) keys[j] = __ldg(ck + j);
        uint32_t kmin = 0xFFFFFFFFu;
        #pragma unroll
        for (int j = 0; j < 16; j++)
            if (keys[j] < kmin) kmin = keys[j];
        float vmin = __uint_as_float(fdec(kmin & 0xFFFFFC00u));
        float thr  = vmin + EPS_MARGIN;
        uint32_t thrkey = fenc(__float_as_uint(thr)) | 0x3FFu;
        int ncand = 0;
        #pragma unroll
        for (int j = 0; j < 16; j++)
            ncand += (keys[j] <= thrkey);
        int bk = (int)(kmin & 0x3FFu);
        if (ncand > 1) {
            const float* xr = inputs + (size_t)(rowBase + tid) * D_DIM;
            float beste = FLT_MAX;
            int   bestk = 0x7FFFFFFF;
            #pragma unroll 4
            for (int j = 0; j < 16; j++) {
                if (keys[j] > thrkey) continue;
                int k = (int)(keys[j] & 0x3FFu);
                const float* cr = g_cT + (size_t)k * D_DIM;
                float dot = 0.0f;
                #pragma unroll 8
                for (int d = 0; d < D_DIM; d++)
                    dot = fmaf(__ldg(xr + d), __ldg(cr + d), dot);
                float e = fmaf(-2.0f, dot, __ldg(g_cnorm + k));
                if (e < beste || (e == beste && k < bestk)) { beste = e; bestk = k; }
            }
            bk = bestk;
        }
        s_bk[tid] = bk;
        atomicAdd(&g_counts[bk], 1);
    }
    __syncthreads();

    // ---- epilogue: ste + sum (q-x)^2 ----
    float ss = 0.0f;
    #pragma unroll
    for (int rr = 0; rr < 8; rr++) {
        const int r = wid * 8 + rr;
        const int bk = s_bk[r];
        const float4* x4 = (const float4*)(inputs + (size_t)(rowBase + r) * D_DIM);
        const float4* q4 = (const float4*)(g_cT + (size_t)bk * D_DIM);
        float4* o4 = (float4*)(out + (size_t)(rowBase + r) * D_DIM);
        #pragma unroll
        for (int h = 0; h < 2; h++) {
            int d4 = lane + h * 32;
            float4 x = x4[d4];
            float4 q = q4[d4];
            float d0 = q.x - x.x, d1 = q.y - x.y, d2 = q.z - x.z, d3 = q.w - x.w;
            float4 o;
            o.x = x.x + d0; o.y = x.y + d1; o.z = x.z + d2; o.w = x.w + d3;
            o4[d4] = o;
            ss = fmaf(d0, d0, ss); ss = fmaf(d1, d1, ss);
            ss = fmaf(d2, d2, ss); ss = fmaf(d3, d3, ss);
        }
    }
    #pragma unroll
    for (int o = 16; o; o >>= 1)
        ss += __shfl_xor_sync(0xFFFFFFFFu, ss, o);
    if (lane == 0) atomicAdd(&g_sumsq, ss);
}

// ============================================================================
__global__ void k_final(float* __restrict__ out, int rows) {
    __shared__ float red[32];
    int tid = threadIdx.x;
    float p = (float)g_counts[tid] / (float)rows;
    float term = -p * logf(p + 1e-10f);
    #pragma unroll
    for (int o = 16; o; o >>= 1)
        term += __shfl_xor_sync(0xFFFFFFFFu, term, o);
    if ((tid & 31) == 0) red[tid >> 5] = term;
    __syncthreads();
    if (tid < 32) {
        float v = red[tid];
        #pragma unroll
        for (int o = 16; o; o >>= 1)
            v += __shfl_xor_sync(0xFFFFFFFFu, v, o);
        if (tid == 0) {
            float mean = g_sumsq / ((float)rows * (float)D_DIM);
            size_t base = (size_t)rows * D_DIM;
            out[base + 0] = expf(v);
            out[base + 1] = mean;
            out[base + 2] = 0.25f * mean;
        }
    }
}

// ============================================================================
extern "C" void kernel_launch(void* const* d_in, const int* in_sizes, int n_in,
                              void* d_out, int out_size) {
    const float* inputs   = (const float*)d_in[0];
    const float* codebook = (const float*)d_in[1];
    float* out = (float*)d_out;
    int rows = in_sizes[0] / D_DIM;      // 32768
    int rowTiles = rows / BM;            // 512

    cudaFuncSetAttribute(k_rank, cudaFuncAttributeMaxDynamicSharedMemorySize, SMEM_MAIN);

    k_init<<<1, 1024>>>();
    k_cnorm<<<K_CODES / 256, 256>>>(codebook);
    k_prep<<<dim3(K_CODES / 32, D_DIM / 32), dim3(32, 32)>>>(codebook);
    k_rank<<<rowTiles * NGROUP, THREADS, SMEM_MAIN>>>(inputs);
    k_tail<<<rowTiles, THREADS>>>(inputs, out);
    k_final<<<1, 1024>>>(out, rows);
}